// round 6
// baseline (speedup 1.0000x reference)
#include <cuda_runtime.h>
#include <cuda_bf16.h>
#include <cstdint>

#define NPTS 100000
#define K3   27
#define MT   128            // points per CTA
#define NTHR 256            // 8 warps: 4(M) x 2(N)
#define ARSTR 36            // A smem row stride (words of bf16x2); 36%32==4 -> conflict-free
#define AARR  (128*ARSTR)   // 4608 words per array (hi or lo)
#define ABUFW (2*AARR)      // 9216 words per A buffer (hi+lo)
#define WBUFW 4096          // words per W chunk buffer (hi 2048 + lo 2048)
#define SMEM_WORDS (2*ABUFW + 2*WBUFW)   // 26624
#define SMEM_BYTES (SMEM_WORDS*4)        // 106496 -> 2 CTAs/SM

// ---------------- device scratch (static, no runtime alloc) ----------------
__device__ __align__(16) unsigned g_xh[(size_t)NPTS * 64];   // x hi, bf16x2 words
__device__ __align__(16) unsigned g_xl[(size_t)NPTS * 64];   // x lo
__device__ __align__(16) unsigned g_hh[(size_t)NPTS * 64];   // h hi
__device__ __align__(16) unsigned g_hl[(size_t)NPTS * 64];   // h lo
__device__ __align__(16) unsigned g_W00p[K3 * 8192];         // per tap: 2 chunks x [hi2048|lo2048]
__device__ __align__(16) unsigned g_WcatB[K3 * 8192];        // per tap: [W01 chunk | W11 chunk]
__device__ __align__(16) unsigned g_W10p[8192];              // 2 chunks
__device__ __align__(16) unsigned g_W12p[4096];              // 1 chunk

// ---------------- helpers ----------------
__device__ __forceinline__ unsigned short f2bf(float f) {
    return __bfloat16_as_ushort(__float2bfloat16_rn(f));
}
__device__ __forceinline__ float bf2f(unsigned short u) {
    return __bfloat162float(__ushort_as_bfloat16(u));
}
// split pair (a,b) into hi word + lo word (bf16x2 each)
__device__ __forceinline__ void split2(float a, float b, unsigned& hi, unsigned& lo) {
    unsigned short ha = f2bf(a), hb = f2bf(b);
    float ra = a - bf2f(ha), rb = b - bf2f(hb);
    hi = (unsigned)ha | ((unsigned)hb << 16);
    lo = (unsigned)f2bf(ra) | ((unsigned)f2bf(rb) << 16);
}
__device__ __forceinline__ unsigned smem_u32(const void* p) {
    unsigned a;
    asm("{ .reg .u64 t; cvta.to.shared.u64 t, %1; cvt.u32.u64 %0, t; }" : "=r"(a) : "l"(p));
    return a;
}
__device__ __forceinline__ void cp16(unsigned dst, const void* src, unsigned srcsize) {
    asm volatile("cp.async.cg.shared.global [%0], [%1], 16, %2;"
                 :: "r"(dst), "l"(src), "r"(srcsize));
}
#define CP_COMMIT() asm volatile("cp.async.commit_group;")
#define CP_WAIT1()  asm volatile("cp.async.wait_group 1;")
#define CP_WAIT0()  asm volatile("cp.async.wait_group 0;")

__device__ __forceinline__ void mma_bf16(float* d, const unsigned* a, unsigned b0, unsigned b1) {
    asm volatile(
        "mma.sync.aligned.m16n8k16.row.col.f32.bf16.bf16.f32 "
        "{%0,%1,%2,%3}, {%4,%5,%6,%7}, {%8,%9}, {%0,%1,%2,%3};\n"
        : "+f"(d[0]), "+f"(d[1]), "+f"(d[2]), "+f"(d[3])
        : "r"(a[0]), "r"(a[1]), "r"(a[2]), "r"(a[3]), "r"(b0), "r"(b1));
}

// B pack offset within one [64k x 64n] chunk's hi array (words):
//   word(c,n) = (c>>4)*512 + n*8 + ((c&7)>>1)*2 + ((c>>3)&1), bf16 slot = c&1
__device__ __forceinline__ int boff(int c, int n) {
    return ((c >> 4) << 9) + (n << 3) + (((c & 7) >> 1) << 1) + ((c >> 3) & 1);
}
// write hi/lo bf16 of v at chunk-relative word off (lo array at +2048 words)
__device__ __forceinline__ void wsplit(unsigned* base, int word, int slot, float v) {
    __nv_bfloat16* p = (__nv_bfloat16*)base;
    unsigned short h = f2bf(v);
    p[(size_t)word * 2 + slot] = __ushort_as_bfloat16(h);
    p[((size_t)word + 2048) * 2 + slot] = __float2bfloat16_rn(v - bf2f(h));
}

// ---------------- prep: split x into bf16 hi/lo ----------------
__global__ void split_x(const float* __restrict__ x) {
    size_t t = (size_t)blockIdx.x * blockDim.x + threadIdx.x;
    if (t >= (size_t)NPTS * 32) return;
    float4 v = ((const float4*)x)[t];
    unsigned h0, l0, h1, l1;
    split2(v.x, v.y, h0, l0);
    split2(v.z, v.w, h1, l1);
    ((uint2*)g_xh)[t] = make_uint2(h0, h1);
    ((uint2*)g_xl)[t] = make_uint2(l0, l1);
}

// ---------------- weight packing ----------------
#define P_W00  (K3 * 8192)
#define P_WCAT (K3 * 8192)
#define P_TOT  (P_W00 + P_WCAT + 8192 + 4096)

__global__ void pack_weights(const float* __restrict__ W00, const float* __restrict__ W01,
                             const float* __restrict__ W11, const float* __restrict__ W10,
                             const float* __restrict__ W12) {
    int t = blockIdx.x * blockDim.x + threadIdx.x;
    if (t < P_W00) {                                    // W00[k][c 0..127][n 0..63]
        int k = t / 8192, rem = t % 8192, c = rem / 64, n = rem % 64, cl = c & 63;
        wsplit(g_W00p, k * 8192 + (c >> 6) * 4096 + boff(cl, n), cl & 1, W00[t]);
        return;
    }
    t -= P_W00;
    if (t < P_WCAT) {                                   // chunk0=W01, chunk1=W11; c 0..63
        int k = t / 8192, rem = t % 8192, half = rem / 4096, r2 = rem % 4096;
        int c = r2 / 64, n = r2 % 64;
        float v = half ? W11[k * 4096 + c * 64 + n] : W01[k * 4096 + c * 64 + n];
        wsplit(g_WcatB, k * 8192 + half * 4096 + boff(c, n), c & 1, v);
        return;
    }
    t -= P_WCAT;
    if (t < 8192) {                                     // W10[c 0..127][n]
        int c = t / 64, n = t % 64, cl = c & 63;
        wsplit(g_W10p, (c >> 6) * 4096 + boff(cl, n), cl & 1, W10[t]);
        return;
    }
    t -= 8192;
    if (t < 4096) { int c = t / 64, n = t % 64; wsplit(g_W12p, boff(c, n), c & 1, W12[t]); }
}

// -------- inner step: [128m x 64k-chunk] x [64k x 64n] with 3-term bf16 split --------
__device__ __forceinline__ void mma_chunk(const unsigned* As, const unsigned* Wb,
                                          float acc[2][4][4], int wm, int wn, int lane) {
    const int gr = lane >> 2, gc = lane & 3;
    #pragma unroll
    for (int g = 0; g < 4; ++g) {
        unsigned ah[2][4], al[2][4];
        #pragma unroll
        for (int mb = 0; mb < 2; ++mb) {
            const int o0 = (wm * 32 + mb * 16 + gr) * ARSTR + g * 8 + gc;
            const int o1 = o0 + 8 * ARSTR;
            ah[mb][0] = As[o0];        ah[mb][1] = As[o1];
            ah[mb][2] = As[o0 + 4];    ah[mb][3] = As[o1 + 4];
            al[mb][0] = As[AARR + o0];     al[mb][1] = As[AARR + o1];
            al[mb][2] = As[AARR + o0 + 4]; al[mb][3] = As[AARR + o1 + 4];
        }
        #pragma unroll
        for (int nt = 0; nt < 4; ++nt) {
            const int bw = g * 512 + (wn * 32 + nt * 8 + gr) * 8 + gc * 2;
            uint2 bh = *(const uint2*)(Wb + bw);
            uint2 bl = *(const uint2*)(Wb + 2048 + bw);
            #pragma unroll
            for (int mb = 0; mb < 2; ++mb) {
                mma_bf16(acc[mb][nt], ah[mb], bh.x, bh.y);
                mma_bf16(acc[mb][nt], ah[mb], bl.x, bl.y);
                mma_bf16(acc[mb][nt], al[mb], bh.x, bh.y);
            }
        }
    }
}

// =============== kernel A: h = [ relu(conv0_0(x)+b00) | relu(x@W10+b10) ] ===============
__global__ __launch_bounds__(NTHR, 2)
void convA(const int* __restrict__ nbr,
           const float* __restrict__ b00, const float* __restrict__ b10) {
    extern __shared__ unsigned sm[];
    unsigned* Asb[2] = { sm, sm + ABUFW };
    unsigned* Wsb[2] = { sm + 2*ABUFW, sm + 2*ABUFW + WBUFW };
    const unsigned aAddr[2] = { smem_u32(Asb[0]), smem_u32(Asb[1]) };
    const unsigned wAddr[2] = { smem_u32(Wsb[0]), smem_u32(Wsb[1]) };

    const int tid = threadIdx.x, lane = tid & 31, warp = tid >> 5;
    const int wm = warp >> 1, wn = warp & 1;
    const int base = blockIdx.x * MT, rows = min(MT, NPTS - base);
    const int r = tid >> 1, q = tid & 1;      // gather: 2 threads/row, 32 ch each

    auto stage = [&](int s) {
        const int b = s & 1, tap = s >> 1, kc = s & 1;
        int idx;
        if (r < rows) idx = (tap < K3) ? __ldg(&nbr[(size_t)(base + r) * K3 + tap]) : (base + r);
        else          idx = NPTS;
        const unsigned sz = (idx < NPTS) ? 16u : 0u;
        const size_t so = (size_t)idx * 64 + kc * 32 + q * 16;   // word offset
        const unsigned dh = aAddr[b] + (unsigned)(r * ARSTR + q * 16) * 4u;
        #pragma unroll
        for (int i = 0; i < 4; ++i) cp16(dh + i * 16, g_xh + so + i * 4, sz);
        #pragma unroll
        for (int i = 0; i < 4; ++i) cp16(dh + AARR * 4 + i * 16, g_xl + so + i * 4, sz);
        const unsigned* Wg = ((tap < K3) ? (g_W00p + tap * 8192) : g_W10p) + kc * 4096;
        #pragma unroll
        for (int j = 0; j < 4; ++j) {
            int w = (j * NTHR + tid) * 4;
            cp16(wAddr[b] + (unsigned)w * 4u, Wg + w, 16u);
        }
        CP_COMMIT();
    };

    float acc0[2][4][4] = {};   // conv0_0 (taps 0..26)
    float acc1[2][4][4] = {};   // 1x1 W10 (tap 27)

    const int S = 56;
    stage(0);
    for (int s = 0; s < S; ++s) {
        if (s + 1 < S) { stage(s + 1); CP_WAIT1(); } else { CP_WAIT0(); }
        __syncthreads();
        mma_chunk(Asb[s & 1], Wsb[s & 1], (s < 54) ? acc0 : acc1, wm, wn, lane);
        __syncthreads();
    }

    // epilogue: relu + bias, split-store h
    #pragma unroll
    for (int mb = 0; mb < 2; ++mb) {
        const int r0 = wm * 32 + mb * 16 + (lane >> 2);
        const int p0 = base + r0, p1 = p0 + 8;
        #pragma unroll
        for (int nt = 0; nt < 4; ++nt) {
            const int col = wn * 32 + nt * 8 + (lane & 3) * 2;
            const float ba0 = __ldg(&b00[col]), ba1 = __ldg(&b00[col + 1]);
            const float bb0 = __ldg(&b10[col]), bb1 = __ldg(&b10[col + 1]);
            unsigned hi, lo;
            if (p0 < NPTS) {
                split2(fmaxf(acc0[mb][nt][0] + ba0, 0.f), fmaxf(acc0[mb][nt][1] + ba1, 0.f), hi, lo);
                g_hh[(size_t)p0 * 64 + (col >> 1)] = hi; g_hl[(size_t)p0 * 64 + (col >> 1)] = lo;
                split2(fmaxf(acc1[mb][nt][0] + bb0, 0.f), fmaxf(acc1[mb][nt][1] + bb1, 0.f), hi, lo);
                g_hh[(size_t)p0 * 64 + 32 + (col >> 1)] = hi; g_hl[(size_t)p0 * 64 + 32 + (col >> 1)] = lo;
            }
            if (p1 < NPTS) {
                split2(fmaxf(acc0[mb][nt][2] + ba0, 0.f), fmaxf(acc0[mb][nt][3] + ba1, 0.f), hi, lo);
                g_hh[(size_t)p1 * 64 + (col >> 1)] = hi; g_hl[(size_t)p1 * 64 + (col >> 1)] = lo;
                split2(fmaxf(acc1[mb][nt][2] + bb0, 0.f), fmaxf(acc1[mb][nt][3] + bb1, 0.f), hi, lo);
                g_hh[(size_t)p1 * 64 + 32 + (col >> 1)] = hi; g_hl[(size_t)p1 * 64 + 32 + (col >> 1)] = lo;
            }
        }
    }
}

// ==== kernel B: out = [conv0_1(h0)+b01 | relu(conv1_1(h1)+b11)@W12+b12] + x ====
__global__ __launch_bounds__(NTHR, 2)
void convB(const int* __restrict__ nbr,
           const float* __restrict__ b01, const float* __restrict__ b11,
           const float* __restrict__ b12, const float* __restrict__ x,
           float* __restrict__ out) {
    extern __shared__ unsigned sm[];
    unsigned* Asb[2] = { sm, sm + ABUFW };
    unsigned* Wsb[2] = { sm + 2*ABUFW, sm + 2*ABUFW + WBUFW };
    const unsigned aAddr[2] = { smem_u32(Asb[0]), smem_u32(Asb[1]) };
    const unsigned wAddr[2] = { smem_u32(Wsb[0]), smem_u32(Wsb[1]) };

    const int tid = threadIdx.x, lane = tid & 31, warp = tid >> 5;
    const int wm = warp >> 1, wn = warp & 1;
    const int base = blockIdx.x * MT, rows = min(MT, NPTS - base);
    const int r = tid >> 1, q = tid & 1;

    auto stage = [&](int s) {
        const int b = s & 1, tap = s >> 1, kc = s & 1;   // kc0: h0@W01, kc1: h1@W11
        const int idx = (r < rows) ? __ldg(&nbr[(size_t)(base + r) * K3 + tap]) : NPTS;
        const unsigned sz = (idx < NPTS) ? 16u : 0u;
        const size_t so = (size_t)idx * 64 + kc * 32 + q * 16;
        const unsigned dh = aAddr[b] + (unsigned)(r * ARSTR + q * 16) * 4u;
        #pragma unroll
        for (int i = 0; i < 4; ++i) cp16(dh + i * 16, g_hh + so + i * 4, sz);
        #pragma unroll
        for (int i = 0; i < 4; ++i) cp16(dh + AARR * 4 + i * 16, g_hl + so + i * 4, sz);
        const unsigned* Wg = g_WcatB + tap * 8192 + kc * 4096;
        #pragma unroll
        for (int j = 0; j < 4; ++j) {
            int w = (j * NTHR + tid) * 4;
            cp16(wAddr[b] + (unsigned)w * 4u, Wg + w, 16u);
        }
        CP_COMMIT();
    };

    float acc0[2][4][4] = {};   // h0 @ W01
    float acc1[2][4][4] = {};   // h1 @ W11 (pre-relu)

    const int S = 54;
    stage(0);
    for (int s = 0; s < S; ++s) {
        if (s + 1 < S) { stage(s + 1); CP_WAIT1(); } else { CP_WAIT0(); }
        __syncthreads();
        mma_chunk(Asb[s & 1], Wsb[s & 1], (s & 1) ? acc1 : acc0, wm, wn, lane);
        __syncthreads();
    }

    // ---- epilogue: store out0 (+b01 +x); stage h1b split into Asb[0] ----
    unsigned* Sst = Asb[0];
    #pragma unroll
    for (int mb = 0; mb < 2; ++mb) {
        const int r0 = wm * 32 + mb * 16 + (lane >> 2), r1 = r0 + 8;
        const int p0 = base + r0, p1 = base + r1;
        #pragma unroll
        for (int nt = 0; nt < 4; ++nt) {
            const int col = wn * 32 + nt * 8 + (lane & 3) * 2;
            const float bh0 = __ldg(&b11[col]), bh1 = __ldg(&b11[col + 1]);
            unsigned hi, lo;
            split2(fmaxf(acc1[mb][nt][0] + bh0, 0.f), fmaxf(acc1[mb][nt][1] + bh1, 0.f), hi, lo);
            Sst[r0 * ARSTR + (col >> 1)] = hi; Sst[AARR + r0 * ARSTR + (col >> 1)] = lo;
            split2(fmaxf(acc1[mb][nt][2] + bh0, 0.f), fmaxf(acc1[mb][nt][3] + bh1, 0.f), hi, lo);
            Sst[r1 * ARSTR + (col >> 1)] = hi; Sst[AARR + r1 * ARSTR + (col >> 1)] = lo;
            const float bo0 = __ldg(&b01[col]), bo1 = __ldg(&b01[col + 1]);
            if (p0 < NPTS) {
                float2 xv = *(const float2*)(x + (size_t)p0 * 128 + col);
                *(float2*)(out + (size_t)p0 * 128 + col) =
                    make_float2(acc0[mb][nt][0] + bo0 + xv.x, acc0[mb][nt][1] + bo1 + xv.y);
            }
            if (p1 < NPTS) {
                float2 xv = *(const float2*)(x + (size_t)p1 * 128 + col);
                *(float2*)(out + (size_t)p1 * 128 + col) =
                    make_float2(acc0[mb][nt][2] + bo0 + xv.x, acc0[mb][nt][3] + bo1 + xv.y);
            }
        }
    }
    // copy packed W12 into Wsb[0]
    #pragma unroll
    for (int j = 0; j < 4; ++j) {
        int w = (j * NTHR + tid) * 4;
        *(uint4*)(Wsb[0] + w) = *(const uint4*)(g_W12p + w);
    }
    __syncthreads();

    // ---- 1x1 epilogue GEMM: acc2 = h1b @ W12 ----
    float acc2[2][4][4] = {};
    mma_chunk(Asb[0], Wsb[0], acc2, wm, wn, lane);

    #pragma unroll
    for (int mb = 0; mb < 2; ++mb) {
        const int r0 = wm * 32 + mb * 16 + (lane >> 2);
        const int p0 = base + r0, p1 = p0 + 8;
        #pragma unroll
        for (int nt = 0; nt < 4; ++nt) {
            const int col = wn * 32 + nt * 8 + (lane & 3) * 2;
            const float bv0 = __ldg(&b12[col]), bv1 = __ldg(&b12[col + 1]);
            if (p0 < NPTS) {
                float2 xv = *(const float2*)(x + (size_t)p0 * 128 + 64 + col);
                *(float2*)(out + (size_t)p0 * 128 + 64 + col) =
                    make_float2(acc2[mb][nt][0] + bv0 + xv.x, acc2[mb][nt][1] + bv1 + xv.y);
            }
            if (p1 < NPTS) {
                float2 xv = *(const float2*)(x + (size_t)p1 * 128 + 64 + col);
                *(float2*)(out + (size_t)p1 * 128 + 64 + col) =
                    make_float2(acc2[mb][nt][2] + bv0 + xv.x, acc2[mb][nt][3] + bv1 + xv.y);
            }
        }
    }
}

// ---------------- launch ----------------
extern "C" void kernel_launch(void* const* d_in, const int* in_sizes, int n_in,
                              void* d_out, int out_size) {
    const float* x   = (const float*)d_in[0];
    const int*   nbr = (const int*)  d_in[1];
    const float* W00 = (const float*)d_in[2];
    const float* b00 = (const float*)d_in[3];
    const float* W01 = (const float*)d_in[4];
    const float* b01 = (const float*)d_in[5];
    const float* W10 = (const float*)d_in[6];
    const float* b10 = (const float*)d_in[7];
    const float* W11 = (const float*)d_in[8];
    const float* b11 = (const float*)d_in[9];
    const float* W12 = (const float*)d_in[10];
    const float* b12 = (const float*)d_in[11];
    float* out = (float*)d_out;

    cudaFuncSetAttribute(convA, cudaFuncAttributeMaxDynamicSharedMemorySize, SMEM_BYTES);
    cudaFuncSetAttribute(convB, cudaFuncAttributeMaxDynamicSharedMemorySize, SMEM_BYTES);

    split_x<<<(NPTS * 32 + 255) / 256, 256>>>(x);
    pack_weights<<<(P_TOT + 255) / 256, 256>>>(W00, W01, W11, W10, W12);
    const int grid = (NPTS + MT - 1) / MT;   // 782
    convA<<<grid, NTHR, SMEM_BYTES>>>(nbr, b00, b10);
    convB<<<grid, NTHR, SMEM_BYTES>>>(nbr, b01, b11, b12, x, out);
}

// round 7
// speedup vs baseline: 1.5546x; 1.5546x over previous
#include <cuda_runtime.h>
#include <cuda_bf16.h>
#include <cstdint>

#define NPTS 100000
#define K3   27
#define MT   128
#define NTHR 256            // 8 warps: 4(M) x 2(N)
#define NSTG 3
// stage layout (words): [A hi 2560 | A lo 2560 | B hi 1280 | B lo 1280]
// A row = 80 bytes (64B data = 32 bf16, 16B pad) -> conflict-free ldmatrix (5r mod 8 perm)
#define STGW  7680
#define STGB  (STGW*4)      // 30720 B
#define ALOB  (2560*4)      // A lo offset within stage (bytes)
#define BOFFB (5120*4)      // B hi offset within stage (bytes)
#define BLOB  (1280*4)      // B lo offset within B region (bytes)
#define SMEM_BYTES (NSTG*STGB)   // 92160 -> 2 CTAs/SM

// ---------------- device scratch ----------------
__device__ __align__(16) unsigned g_xh[(size_t)NPTS * 64];   // x hi (bf16x2 words)
__device__ __align__(16) unsigned g_xl[(size_t)NPTS * 64];   // x lo
__device__ __align__(16) unsigned g_hh[(size_t)NPTS * 64];   // h hi
__device__ __align__(16) unsigned g_hl[(size_t)NPTS * 64];   // h lo
// weight chunks stored as exact smem B-region images (incl. pad): 2560 words = [hi1280|lo1280]
__device__ __align__(16) unsigned g_W00p[K3 * 10240];        // 27 taps x 4 chunks
__device__ __align__(16) unsigned g_WcatB[K3 * 10240];       // chunks 0,1 = W01; 2,3 = W11
__device__ __align__(16) unsigned g_W10p[10240];             // 4 chunks
__device__ __align__(16) unsigned g_W12p[5120];              // 2 chunks

// ---------------- helpers ----------------
__device__ __forceinline__ unsigned short f2bf(float f) {
    return __bfloat16_as_ushort(__float2bfloat16_rn(f));
}
__device__ __forceinline__ float bf2f(unsigned short u) {
    return __bfloat162float(__ushort_as_bfloat16(u));
}
__device__ __forceinline__ void split2(float a, float b, unsigned& hi, unsigned& lo) {
    unsigned short ha = f2bf(a), hb = f2bf(b);
    float ra = a - bf2f(ha), rb = b - bf2f(hb);
    hi = (unsigned)ha | ((unsigned)hb << 16);
    lo = (unsigned)f2bf(ra) | ((unsigned)f2bf(rb) << 16);
}
__device__ __forceinline__ unsigned smem_u32(const void* p) {
    unsigned a;
    asm("{ .reg .u64 t; cvta.to.shared.u64 t, %1; cvt.u32.u64 %0, t; }" : "=r"(a) : "l"(p));
    return a;
}
__device__ __forceinline__ void cp16(unsigned dst, const void* src, unsigned srcsize) {
    asm volatile("cp.async.cg.shared.global [%0], [%1], 16, %2;"
                 :: "r"(dst), "l"(src), "r"(srcsize));
}
#define CP_COMMIT() asm volatile("cp.async.commit_group;")
#define CP_WAIT1()  asm volatile("cp.async.wait_group 1;")
#define CP_WAIT0()  asm volatile("cp.async.wait_group 0;")

__device__ __forceinline__ void ldsm4(unsigned& r0, unsigned& r1, unsigned& r2, unsigned& r3,
                                      unsigned a) {
    asm volatile("ldmatrix.sync.aligned.m8n8.x4.shared.b16 {%0,%1,%2,%3}, [%4];"
                 : "=r"(r0), "=r"(r1), "=r"(r2), "=r"(r3) : "r"(a));
}
__device__ __forceinline__ void mma_bf16(float* d, const unsigned* a, unsigned b0, unsigned b1) {
    asm volatile(
        "mma.sync.aligned.m16n8k16.row.col.f32.bf16.bf16.f32 "
        "{%0,%1,%2,%3}, {%4,%5,%6,%7}, {%8,%9}, {%0,%1,%2,%3};\n"
        : "+f"(d[0]), "+f"(d[1]), "+f"(d[2]), "+f"(d[3])
        : "r"(a[0]), "r"(a[1]), "r"(a[2]), "r"(a[3]), "r"(b0), "r"(b1));
}

// write hi/lo bf16 of v into a weight chunk image (chunkBase word array)
__device__ __forceinline__ void wsplit(unsigned* chunkBase, int off, int slot, float v) {
    __nv_bfloat16* ph = (__nv_bfloat16*)(chunkBase + off);
    __nv_bfloat16* pl = (__nv_bfloat16*)(chunkBase + 1280 + off);
    unsigned short h = f2bf(v);
    ph[slot] = __ushort_as_bfloat16(h);
    pl[slot] = __float2bfloat16_rn(v - bf2f(h));
}

// ---------------- prep: split x into bf16 hi/lo ----------------
__global__ void split_x(const float* __restrict__ x) {
    size_t t = (size_t)blockIdx.x * blockDim.x + threadIdx.x;
    if (t >= (size_t)NPTS * 32) return;
    float4 v = ((const float4*)x)[t];
    unsigned h0, l0, h1, l1;
    split2(v.x, v.y, h0, l0);
    split2(v.z, v.w, h1, l1);
    ((uint2*)g_xh)[t] = make_uint2(h0, h1);
    ((uint2*)g_xl)[t] = make_uint2(l0, l1);
}

// ---------------- weight packing ----------------
#define P_W00  (K3 * 128 * 64)
#define P_WCAT (K3 * 64 * 128)
#define P_TOT  (P_W00 + P_WCAT + 128*64 + 64*64)

__global__ void pack_weights(const float* __restrict__ W00, const float* __restrict__ W01,
                             const float* __restrict__ W11, const float* __restrict__ W10,
                             const float* __restrict__ W12) {
    int t = blockIdx.x * blockDim.x + threadIdx.x;
    if (t < P_W00) {                       // W00[k][c 0..127][n 0..63]
        int k = t / 8192, rem = t % 8192, c = rem / 64, n = rem % 64;
        wsplit(g_W00p + k * 10240 + (c >> 5) * 2560,
               n * 20 + ((c & 31) >> 1), c & 1, W00[t]);
        return;
    }
    t -= P_W00;
    if (t < P_WCAT) {                      // half0 = W01, half1 = W11; c 0..63
        int k = t / 8192, rem = t % 8192, half = rem / 4096, r2 = rem % 4096;
        int c = r2 / 64, n = r2 % 64;
        float v = half ? W11[k * 4096 + c * 64 + n] : W01[k * 4096 + c * 64 + n];
        wsplit(g_WcatB + k * 10240 + (half * 2 + (c >> 5)) * 2560,
               n * 20 + ((c & 31) >> 1), c & 1, v);
        return;
    }
    t -= P_WCAT;
    if (t < 128 * 64) {                    // W10[c 0..127][n]
        int c = t / 64, n = t % 64;
        wsplit(g_W10p + (c >> 5) * 2560, n * 20 + ((c & 31) >> 1), c & 1, W10[t]);
        return;
    }
    t -= 128 * 64;
    if (t < 64 * 64) {
        int c = t / 64, n = t % 64;
        wsplit(g_W12p + (c >> 5) * 2560, n * 20 + ((c & 31) >> 1), c & 1, W12[t]);
    }
}

// ---- inner stage: [128m x 32k] x [32k x 64n], 3-term bf16 split, ldmatrix frags ----
__device__ __forceinline__ void mma_stage(unsigned Ab, unsigned Bb,
                                          float acc[2][4][4],
                                          unsigned aOff, unsigned bOff) {
    #pragma unroll
    for (int g = 0; g < 2; ++g) {
        unsigned ah[2][4], al[2][4], bh[2][4], bl[2][4];
        #pragma unroll
        for (int mb = 0; mb < 2; ++mb) {
            unsigned a = Ab + aOff + g * 32 + mb * 1280;
            ldsm4(ah[mb][0], ah[mb][1], ah[mb][2], ah[mb][3], a);
            ldsm4(al[mb][0], al[mb][1], al[mb][2], al[mb][3], a + ALOB);
        }
        #pragma unroll
        for (int p = 0; p < 2; ++p) {
            unsigned b = Bb + bOff + g * 32 + p * 1280;
            ldsm4(bh[p][0], bh[p][1], bh[p][2], bh[p][3], b);
            ldsm4(bl[p][0], bl[p][1], bl[p][2], bl[p][3], b + BLOB);
        }
        #pragma unroll
        for (int mb = 0; mb < 2; ++mb)
            #pragma unroll
            for (int nt = 0; nt < 4; ++nt) {
                const int p = nt >> 1, u = (nt & 1) * 2;
                mma_bf16(acc[mb][nt], ah[mb], bh[p][u], bh[p][u + 1]);
                mma_bf16(acc[mb][nt], ah[mb], bl[p][u], bl[p][u + 1]);
                mma_bf16(acc[mb][nt], al[mb], bh[p][u], bh[p][u + 1]);
            }
    }
}

// =============== kernel A: h = [ relu(conv0_0(x)+b00) | relu(x@W10+b10) ] ===============
__global__ __launch_bounds__(NTHR, 2)
void convA(const int* __restrict__ nbr,
           const float* __restrict__ b00, const float* __restrict__ b10) {
    extern __shared__ unsigned sm[];
    const unsigned sA = smem_u32(sm);
    const int tid = threadIdx.x, lane = tid & 31, warp = tid >> 5;
    const int wm = warp >> 1, wn = warp & 1;
    const int base = blockIdx.x * MT, rows = min(MT, NPTS - base);
    const int r = tid >> 1, q = tid & 1;

    const unsigned aOff = (unsigned)((wm * 32 + ((lane >> 3) & 1) * 8 + (lane & 7)) * 80
                                     + ((lane >> 4) & 1) * 16);
    const unsigned bOff = (unsigned)((wn * 32 + ((lane >> 4) & 1) * 8 + (lane & 7)) * 80
                                     + ((lane >> 3) & 1) * 16);

    auto stage = [&](int s) {
        const unsigned bufA = sA + (unsigned)(s % NSTG) * STGB;
        const int tap = s >> 2, kc = s & 3;
        int idx;
        if (r < rows) idx = (tap < K3) ? __ldg(&nbr[(size_t)(base + r) * K3 + tap]) : (base + r);
        else          idx = NPTS;
        const unsigned sz = (idx < NPTS) ? 16u : 0u;
        const size_t so = (size_t)idx * 64 + kc * 16 + q * 8;
        const unsigned dA = bufA + (unsigned)(r * 80 + q * 32);
        cp16(dA,            g_xh + so,     sz);
        cp16(dA + 16,       g_xh + so + 4, sz);
        cp16(dA + ALOB,     g_xl + so,     sz);
        cp16(dA + ALOB + 16, g_xl + so + 4, sz);
        if (tid < 128) {
            const unsigned* Wg = ((tap < K3) ? (g_W00p + tap * 10240) : g_W10p) + kc * 2560;
            #pragma unroll
            for (int j = 0; j < 5; ++j) {
                const int i = j * 128 + tid;
                cp16(bufA + BOFFB + (unsigned)i * 16u, Wg + i * 4, 16u);
            }
        }
        CP_COMMIT();
    };

    float acc0[2][4][4] = {};   // conv0_0 (taps 0..26)
    float acc1[2][4][4] = {};   // W10 (tap 27)

    const int S = 112;          // 28 taps x 4 k-chunks
    stage(0); stage(1);
    for (int s = 0; s < S; ++s) {
        if (s < S - 1) { CP_WAIT1(); } else { CP_WAIT0(); }
        __syncthreads();
        if (s + 2 < S) stage(s + 2);
        const unsigned Ab = sA + (unsigned)(s % NSTG) * STGB;
        mma_stage(Ab, Ab + BOFFB, ((s >> 2) < K3) ? acc0 : acc1, aOff, bOff);
    }

    // epilogue: relu + bias, split-store h
    #pragma unroll
    for (int mb = 0; mb < 2; ++mb) {
        const int r0 = wm * 32 + mb * 16 + (lane >> 2);
        const int p0 = base + r0, p1 = p0 + 8;
        #pragma unroll
        for (int nt = 0; nt < 4; ++nt) {
            const int col = wn * 32 + nt * 8 + (lane & 3) * 2;
            const float ba0 = __ldg(&b00[col]), ba1 = __ldg(&b00[col + 1]);
            const float bb0 = __ldg(&b10[col]), bb1 = __ldg(&b10[col + 1]);
            unsigned hi, lo;
            if (p0 < NPTS) {
                split2(fmaxf(acc0[mb][nt][0] + ba0, 0.f), fmaxf(acc0[mb][nt][1] + ba1, 0.f), hi, lo);
                g_hh[(size_t)p0 * 64 + (col >> 1)] = hi; g_hl[(size_t)p0 * 64 + (col >> 1)] = lo;
                split2(fmaxf(acc1[mb][nt][0] + bb0, 0.f), fmaxf(acc1[mb][nt][1] + bb1, 0.f), hi, lo);
                g_hh[(size_t)p0 * 64 + 32 + (col >> 1)] = hi; g_hl[(size_t)p0 * 64 + 32 + (col >> 1)] = lo;
            }
            if (p1 < NPTS) {
                split2(fmaxf(acc0[mb][nt][2] + ba0, 0.f), fmaxf(acc0[mb][nt][3] + ba1, 0.f), hi, lo);
                g_hh[(size_t)p1 * 64 + (col >> 1)] = hi; g_hl[(size_t)p1 * 64 + (col >> 1)] = lo;
                split2(fmaxf(acc1[mb][nt][2] + bb0, 0.f), fmaxf(acc1[mb][nt][3] + bb1, 0.f), hi, lo);
                g_hh[(size_t)p1 * 64 + 32 + (col >> 1)] = hi; g_hl[(size_t)p1 * 64 + 32 + (col >> 1)] = lo;
            }
        }
    }
}

// ==== kernel B: out = [conv0_1(h0)+b01 | relu(conv1_1(h1)+b11)@W12+b12] + x ====
__global__ __launch_bounds__(NTHR, 2)
void convB(const int* __restrict__ nbr,
           const float* __restrict__ b01, const float* __restrict__ b11,
           const float* __restrict__ b12, const float* __restrict__ x,
           float* __restrict__ out) {
    extern __shared__ unsigned sm[];
    const unsigned sA = smem_u32(sm);
    const int tid = threadIdx.x, lane = tid & 31, warp = tid >> 5;
    const int wm = warp >> 1, wn = warp & 1;
    const int base = blockIdx.x * MT, rows = min(MT, NPTS - base);
    const int r = tid >> 1, q = tid & 1;

    const unsigned aOff = (unsigned)((wm * 32 + ((lane >> 3) & 1) * 8 + (lane & 7)) * 80
                                     + ((lane >> 4) & 1) * 16);
    const unsigned bOff = (unsigned)((wn * 32 + ((lane >> 4) & 1) * 8 + (lane & 7)) * 80
                                     + ((lane >> 3) & 1) * 16);

    auto stage = [&](int s) {
        const unsigned bufA = sA + (unsigned)(s % NSTG) * STGB;
        const int tap = s >> 2, kc = s & 3;       // kc 0,1: h0@W01; 2,3: h1@W11
        const int idx = (r < rows) ? __ldg(&nbr[(size_t)(base + r) * K3 + tap]) : NPTS;
        const unsigned sz = (idx < NPTS) ? 16u : 0u;
        const size_t so = (size_t)idx * 64 + kc * 16 + q * 8;   // h = [h0|h1], kc*16 spans both
        const unsigned dA = bufA + (unsigned)(r * 80 + q * 32);
        cp16(dA,             g_hh + so,     sz);
        cp16(dA + 16,        g_hh + so + 4, sz);
        cp16(dA + ALOB,      g_hl + so,     sz);
        cp16(dA + ALOB + 16, g_hl + so + 4, sz);
        if (tid < 128) {
            const unsigned* Wg = g_WcatB + tap * 10240 + kc * 2560;
            #pragma unroll
            for (int j = 0; j < 5; ++j) {
                const int i = j * 128 + tid;
                cp16(bufA + BOFFB + (unsigned)i * 16u, Wg + i * 4, 16u);
            }
        }
        CP_COMMIT();
    };

    float acc0[2][4][4] = {};   // h0 @ W01
    float acc1[2][4][4] = {};   // h1 @ W11 (pre-relu)

    const int S = 108;          // 27 taps x 4 k-chunks
    stage(0); stage(1);
    for (int s = 0; s < S; ++s) {
        if (s < S - 1) { CP_WAIT1(); } else { CP_WAIT0(); }
        __syncthreads();
        if (s + 2 < S) stage(s + 2);
        const unsigned Ab = sA + (unsigned)(s % NSTG) * STGB;
        mma_stage(Ab, Ab + BOFFB, ((s & 3) < 2) ? acc0 : acc1, aOff, bOff);
    }

    // ---- epilogue: store out0 (+b01 +x); stage h1b split into buffers 0/1 A regions ----
    #pragma unroll
    for (int mb = 0; mb < 2; ++mb) {
        const int r0 = wm * 32 + mb * 16 + (lane >> 2), r1 = r0 + 8;
        const int p0 = base + r0, p1 = base + r1;
        #pragma unroll
        for (int nt = 0; nt < 4; ++nt) {
            const int col = wn * 32 + nt * 8 + (lane & 3) * 2;     // 0..63, even
            const int ch = col >> 5, kl = col & 31;
            unsigned* bA = sm + ch * STGW;                          // stage ch A-hi words
            const float bh0 = __ldg(&b11[col]), bh1 = __ldg(&b11[col + 1]);
            unsigned hi, lo;
            split2(fmaxf(acc1[mb][nt][0] + bh0, 0.f), fmaxf(acc1[mb][nt][1] + bh1, 0.f), hi, lo);
            bA[r0 * 20 + (kl >> 1)] = hi; bA[2560 + r0 * 20 + (kl >> 1)] = lo;
            split2(fmaxf(acc1[mb][nt][2] + bh0, 0.f), fmaxf(acc1[mb][nt][3] + bh1, 0.f), hi, lo);
            bA[r1 * 20 + (kl >> 1)] = hi; bA[2560 + r1 * 20 + (kl >> 1)] = lo;
            const float bo0 = __ldg(&b01[col]), bo1 = __ldg(&b01[col + 1]);
            if (p0 < NPTS) {
                float2 xv = *(const float2*)(x + (size_t)p0 * 128 + col);
                *(float2*)(out + (size_t)p0 * 128 + col) =
                    make_float2(acc0[mb][nt][0] + bo0 + xv.x, acc0[mb][nt][1] + bo1 + xv.y);
            }
            if (p1 < NPTS) {
                float2 xv = *(const float2*)(x + (size_t)p1 * 128 + col);
                *(float2*)(out + (size_t)p1 * 128 + col) =
                    make_float2(acc0[mb][nt][2] + bo0 + xv.x, acc0[mb][nt][3] + bo1 + xv.y);
            }
        }
    }
    // copy W12 chunk images into buffers 0/1 B regions
    #pragma unroll
    for (int j = 0; j < 5; ++j) {
        const int w = (j * 256 + tid) * 4;          // word index, < 5120
        const int ch = w / 2560, off = w % 2560;
        *(uint4*)(sm + ch * STGW + 5120 + off) = *(const uint4*)(g_W12p + w);
    }
    __syncthreads();

    // ---- 1x1 epilogue GEMM: acc2 = h1b @ W12 (2 chunks) ----
    float acc2[2][4][4] = {};
    #pragma unroll
    for (int ch = 0; ch < 2; ++ch) {
        const unsigned Ab = sA + (unsigned)ch * STGB;
        mma_stage(Ab, Ab + BOFFB, acc2, aOff, bOff);
    }

    #pragma unroll
    for (int mb = 0; mb < 2; ++mb) {
        const int r0 = wm * 32 + mb * 16 + (lane >> 2);
        const int p0 = base + r0, p1 = p0 + 8;
        #pragma unroll
        for (int nt = 0; nt < 4; ++nt) {
            const int col = wn * 32 + nt * 8 + (lane & 3) * 2;
            const float bv0 = __ldg(&b12[col]), bv1 = __ldg(&b12[col + 1]);
            if (p0 < NPTS) {
                float2 xv = *(const float2*)(x + (size_t)p0 * 128 + 64 + col);
                *(float2*)(out + (size_t)p0 * 128 + 64 + col) =
                    make_float2(acc2[mb][nt][0] + bv0 + xv.x, acc2[mb][nt][1] + bv1 + xv.y);
            }
            if (p1 < NPTS) {
                float2 xv = *(const float2*)(x + (size_t)p1 * 128 + 64 + col);
                *(float2*)(out + (size_t)p1 * 128 + 64 + col) =
                    make_float2(acc2[mb][nt][2] + bv0 + xv.x, acc2[mb][nt][3] + bv1 + xv.y);
            }
        }
    }
}

// ---------------- launch ----------------
extern "C" void kernel_launch(void* const* d_in, const int* in_sizes, int n_in,
                              void* d_out, int out_size) {
    const float* x   = (const float*)d_in[0];
    const int*   nbr = (const int*)  d_in[1];
    const float* W00 = (const float*)d_in[2];
    const float* b00 = (const float*)d_in[3];
    const float* W01 = (const float*)d_in[4];
    const float* b01 = (const float*)d_in[5];
    const float* W10 = (const float*)d_in[6];
    const float* b10 = (const float*)d_in[7];
    const float* W11 = (const float*)d_in[8];
    const float* b11 = (const float*)d_in[9];
    const float* W12 = (const float*)d_in[10];
    const float* b12 = (const float*)d_in[11];
    float* out = (float*)d_out;

    cudaFuncSetAttribute(convA, cudaFuncAttributeMaxDynamicSharedMemorySize, SMEM_BYTES);
    cudaFuncSetAttribute(convB, cudaFuncAttributeMaxDynamicSharedMemorySize, SMEM_BYTES);

    split_x<<<(NPTS * 32 + 255) / 256, 256>>>(x);
    pack_weights<<<(P_TOT + 255) / 256, 256>>>(W00, W01, W11, W10, W12);
    const int grid = (NPTS + MT - 1) / MT;   // 782
    convA<<<grid, NTHR, SMEM_BYTES>>>(nbr, b00, b10);
    convB<<<grid, NTHR, SMEM_BYTES>>>(nbr, b01, b11, b12, x, out);
}